// round 2
// baseline (speedup 1.0000x reference)
#include <cuda_runtime.h>
#include <stdint.h>
#include <math.h>

// ---------------- problem constants ----------------
#define HW_    32768      // 128*256 downsampled pixels per image
#define NCLS_  19
#define NVIEW  50
#define NT     38         // 2 * 19 tiles
#define NR     1900       // NT * NVIEW rows
#define NCH    256        // channels

// RNG scheme: 0 = partitionable, low word (o1)   [tested R1: mismatch]
//             1 = partitionable, first word (o0)
//             2 = legacy split-counter scheme: pair (hw, hw+32768), n=0 -> o0, n=1 -> o1
#define RNG_SCHEME 2

// ---------------- scratch (static device memory; no allocation) ----------------
__device__ unsigned long long g_list[(size_t)NT * HW_];   // 10 MB
__device__ int   g_cnt[NT];
__device__ int   g_sel[NT * NVIEW];
__device__ float g_feat[2][NR * NCH];                     // normalized fcf / fof
__device__ float g_dots[3][(size_t)NR * NR];              // 43.3 MB, scaled logits (dot*10)
__device__ float g_Spart[3][NR * 32];                     // per-(loss,row) partial exp sums (30 col tiles)
__device__ float g_rowloss[3 * NR];

// loss z: 0 = cm (fcf@fof^T), 1 = vis (fcf@fcf^T), 2 = aux (fof@fof^T)
__device__ __constant__ int c_AS[3] = {0, 0, 1};
__device__ __constant__ int c_BS[3] = {1, 0, 1};

// ---------------- threefry2x32, key = jax.random.key(42) = (0, 42) ----------------
__device__ __forceinline__ void threefry2x32(uint32_t c0, uint32_t c1,
                                             uint32_t &o0, uint32_t &o1) {
  const uint32_t ks0 = 0u, ks1 = 42u;
  const uint32_t ks2 = 0u ^ 42u ^ 0x1BD11BDAu;
  uint32_t x0 = c0 + ks0, x1 = c1 + ks1;
#define TFR(r) { x0 += x1; x1 = (x1 << (r)) | (x1 >> (32 - (r))); x1 ^= x0; }
  TFR(13) TFR(15) TFR(26) TFR(6)
  x0 += ks1; x1 += ks2 + 1u;
  TFR(17) TFR(29) TFR(16) TFR(24)
  x0 += ks2; x1 += ks0 + 2u;
  TFR(13) TFR(15) TFR(26) TFR(6)
  x0 += ks0; x1 += ks1 + 3u;
  TFR(17) TFR(29) TFR(16) TFR(24)
  x0 += ks1; x1 += ks2 + 4u;
  TFR(13) TFR(15) TFR(26) TFR(6)
  x0 += ks2; x1 += ks0 + 5u;
#undef TFR
  o0 = x0; o1 = x1;
}

// ---------------- K0: zero counters ----------------
__global__ void k_zero() {
  if (threadIdx.x < NT) g_cnt[threadIdx.x] = 0;
}

// ---------------- K1: rand keys + per-class compaction ----------------
// key64 = (rand_mantissa << 32) | hw  reproduces stable argsort order exactly.
__global__ __launch_bounds__(256) void k_keys(const int* __restrict__ label) {
#if RNG_SCHEME == 2
  // legacy: threefry_2x32 splits iota(65536) in half -> lanes (hw, hw+32768);
  // output is concat(o0_array, o1_array): row n=0 <- o0, row n=1 <- o1.
  int hw = blockIdx.x * blockDim.x + threadIdx.x;
  if (hw >= HW_) return;
  uint32_t o0, o1;
  threefry2x32((uint32_t)hw, (uint32_t)(hw + HW_), o0, o1);
  uint32_t bitsArr[2] = {o0, o1};
  #pragma unroll
  for (int n = 0; n < 2; n++) {
    uint32_t m = bitsArr[n] >> 9;
    int lbl = label[n * 524288 + (hw >> 8) * 4096 + (hw & 255) * 4];
    int t = n * NCLS_ + lbl;
    int pos = atomicAdd(&g_cnt[t], 1);
    g_list[(size_t)t * HW_ + pos] = ((unsigned long long)m << 32) | (unsigned)hw;
  }
#else
  int idx = blockIdx.x * blockDim.x + threadIdx.x;  // flat index into (2, 32768)
  if (idx >= 2 * HW_) return;
  uint32_t o0, o1;
  threefry2x32(0u, (uint32_t)idx, o0, o1);          // counter = (idx>>32, idx) = (0, idx)
#if RNG_SCHEME == 0
  uint32_t bits = o1;
#else
  uint32_t bits = o0;
#endif
  uint32_t m = bits >> 9;                            // ordering of rand == ordering of mantissa
  int n = idx >> 15;
  int hw = idx & (HW_ - 1);
  int lbl = label[n * 524288 + (hw >> 8) * 4096 + (hw & 255) * 4];
  int t = n * NCLS_ + lbl;
  int pos = atomicAdd(&g_cnt[t], 1);
  g_list[(size_t)t * HW_ + pos] = ((unsigned long long)m << 32) | (unsigned)hw;
#endif
}

// ---------------- K2: top-50 smallest keys per (n, class) ----------------
__global__ __launch_bounds__(256) void k_select(const int* __restrict__ label) {
  int t = blockIdx.x;
  int tid = threadIdx.x;
  int cnt = g_cnt[t];
  int lim = min(cnt, NVIEW);
  const unsigned long long* lst = &g_list[(size_t)t * HW_];

  long long loc[16];
  int nl = 0;
  for (int idx = tid; idx < cnt && nl < 16; idx += 256) loc[nl++] = (long long)lst[idx];
  bool spill = (cnt > 16 * 256);

  __shared__ long long red[256];
  __shared__ long long s_best;
  long long prev = -1;
  for (int rr = 0; rr < NVIEW; rr++) {
    long long best = 0x7fffffffffffffffLL;
    if (rr < lim) {
      for (int q = 0; q < nl; q++) { long long k = loc[q]; if (k > prev && k < best) best = k; }
      if (spill)
        for (int idx = tid + 16 * 256; idx < cnt; idx += 256) {
          long long k = (long long)lst[idx];
          if (k > prev && k < best) best = k;
        }
    }
    red[tid] = best;
    __syncthreads();
    for (int s = 128; s > 0; s >>= 1) {
      if (tid < s) red[tid] = min(red[tid], red[tid + s]);
      __syncthreads();
    }
    if (tid == 0) {
      s_best = red[0];
      if (rr < lim) g_sel[t * NVIEW + rr] = (int)(red[0] & 0xffffffffLL);
    }
    __syncthreads();
    prev = s_best;
  }
  // padding (class with < 50 pixels): stable argsort puts non-class pixels (key 2.0)
  // in ascending hw order. Never triggers for this input; kept for exactness.
  if (tid == 0 && cnt < NVIEW) {
    int n = t / NCLS_, cls = t % NCLS_, fill = cnt;
    for (int hw = 0; hw < HW_ && fill < NVIEW; hw++) {
      int lbl = label[n * 524288 + (hw >> 8) * 4096 + (hw & 255) * 4];
      if (lbl != cls) g_sel[t * NVIEW + fill++] = hw;
    }
  }
}

// ---------------- K3: gather + L2 normalize -> g_feat[mod][row][ch] ----------------
__global__ __launch_bounds__(256) void k_gather(const float* __restrict__ colorf,
                                                const float* __restrict__ otherf) {
  int row = blockIdx.x;        // 0..1899
  int mod = blockIdx.y;        // 0 = color (fcf), 1 = other (fof)
  int t = row / NVIEW, v = row % NVIEW, n = t / NCLS_;
  int p = g_sel[t * NVIEW + v];
  const float* f = mod ? otherf : colorf;
  float val = f[((size_t)n * NCH + threadIdx.x) * HW_ + p];
  float sq = val * val;
  #pragma unroll
  for (int o = 16; o; o >>= 1) sq += __shfl_xor_sync(0xffffffffu, sq, o);
  __shared__ float ws[8];
  if ((threadIdx.x & 31) == 0) ws[threadIdx.x >> 5] = sq;
  __syncthreads();
  __shared__ float s_inv;
  if (threadIdx.x == 0) {
    float s = 0.f;
    #pragma unroll
    for (int i = 0; i < 8; i++) s += ws[i];
    s_inv = 1.0f / fmaxf(sqrtf(s), 1e-12f);
  }
  __syncthreads();
  g_feat[mod][row * NCH + threadIdx.x] = val * s_inv;
}

// ---------------- K4: tiled GEMM, store scaled logits + per-row exp partials ----------------
// grid (30 coltiles, 30 rowtiles, 3 losses), 256 threads, 64x64 tile, 4x4 per thread.
__global__ __launch_bounds__(256) void k_gemm() {
  int ct = blockIdx.x, rt = blockIdx.y, z = blockIdx.z;
  const float* __restrict__ A = g_feat[c_AS[z]];
  const float* __restrict__ B = g_feat[c_BS[z]];
  int i0 = rt * 64, j0 = ct * 64;
  __shared__ float As[64][33];
  __shared__ float Bs[64][33];
  __shared__ float rowsum[64];
  int tid = threadIdx.x;
  int ty = tid >> 4, tx = tid & 15;

  float acc[4][4];
  #pragma unroll
  for (int a = 0; a < 4; a++)
    #pragma unroll
    for (int b = 0; b < 4; b++) acc[a][b] = 0.f;

  for (int k0 = 0; k0 < NCH; k0 += 32) {
    #pragma unroll
    for (int e = 0; e < 8; e++) {
      int idx = tid + e * 256;
      int r = idx >> 5, cc = idx & 31;
      int gi = i0 + r, gj = j0 + r;
      As[r][cc] = (gi < NR) ? A[gi * NCH + k0 + cc] : 0.f;
      Bs[r][cc] = (gj < NR) ? B[gj * NCH + k0 + cc] : 0.f;
    }
    __syncthreads();
    #pragma unroll
    for (int kk = 0; kk < 32; kk++) {
      float av[4], bv[4];
      #pragma unroll
      for (int u = 0; u < 4; u++) { av[u] = As[ty * 4 + u][kk]; bv[u] = Bs[tx * 4 + u][kk]; }
      #pragma unroll
      for (int a = 0; a < 4; a++)
        #pragma unroll
        for (int b = 0; b < 4; b++) acc[a][b] = fmaf(av[a], bv[b], acc[a][b]);
    }
    __syncthreads();
  }

  // epilogue: write scaled logits (dot * 10), reduce exp sums per row (deterministic shfl tree)
  #pragma unroll
  for (int a = 0; a < 4; a++) {
    int gi = i0 + ty * 4 + a;
    float4 st;
    float es = 0.f;
    #pragma unroll
    for (int b = 0; b < 4; b++) {
      float d10 = acc[a][b] * 10.0f;
      ((float*)&st)[b] = d10;
      int gj = j0 + tx * 4 + b;
      if (gj < NR) es += expf(d10);
    }
    // reduce over the 16 tx lanes sharing this row group (offsets stay inside 16-lane half)
    #pragma unroll
    for (int o = 8; o; o >>= 1) es += __shfl_xor_sync(0xffffffffu, es, o);
    if (gi < NR) {
      int gj = j0 + tx * 4;
      if (gj < NR) *(float4*)&g_dots[z][(size_t)gi * NR + gj] = st;
      if (tx == 0) rowsum[ty * 4 + a] = es;
    }
  }
  __syncthreads();
  if (tid < 64 && i0 + tid < NR) g_Spart[z][(i0 + tid) * 32 + ct] = rowsum[tid];
}

// ---------------- K5: per-row InfoNCE ----------------
// grid (1900 rows, 3 losses), 128 threads. 100 positive columns per row.
__global__ __launch_bounds__(128) void k_loss() {
  int i = blockIdx.x, z = blockIdx.y;
  int tid = threadIdx.x;
  int ci = (i / NVIEW) % NCLS_;
  int j = -1;
  float d = 0.f, e = 0.f;
  if (tid < 100) {
    j = (tid < 50) ? ci * NVIEW + tid : (NCLS_ + ci) * NVIEW + (tid - 50);
    d = g_dots[z][(size_t)i * NR + j];
    e = expf(d);
  }
  float sa = (tid < 30) ? g_Spart[z][i * 32 + tid] : 0.f;

  float v1 = e, v2 = sa;
  #pragma unroll
  for (int o = 16; o; o >>= 1) {
    v1 += __shfl_xor_sync(0xffffffffu, v1, o);
    v2 += __shfl_xor_sync(0xffffffffu, v2, o);
  }
  __shared__ float shE[4], shS[4];
  if ((tid & 31) == 0) { shE[tid >> 5] = v1; shS[tid >> 5] = v2; }
  __syncthreads();
  float S_pos = shE[0] + shE[1] + shE[2] + shE[3];
  float S_all = shS[0] + shS[1] + shS[2] + shS[3];
  float S_neg = S_all - S_pos;   // sum of exp over different-class columns

  float contrib = 0.f;
  if (tid < 100 && j != i) contrib = d - logf(e + S_neg);
  #pragma unroll
  for (int o = 16; o; o >>= 1) contrib += __shfl_xor_sync(0xffffffffu, contrib, o);
  __shared__ float shC[4];
  if ((tid & 31) == 0) shC[tid >> 5] = contrib;
  __syncthreads();
  if (tid == 0) {
    float s = shC[0] + shC[1] + shC[2] + shC[3];
    g_rowloss[z * NR + i] = -s / 99.0f;   // pos count is always 99
  }
}

// ---------------- K6: final mean per loss ----------------
__global__ __launch_bounds__(256) void k_final(float* __restrict__ out) {
  int z = blockIdx.x, tid = threadIdx.x;
  float s = 0.f;
  for (int i = tid; i < NR; i += 256) s += g_rowloss[z * NR + i];
  #pragma unroll
  for (int o = 16; o; o >>= 1) s += __shfl_xor_sync(0xffffffffu, s, o);
  __shared__ float sh[8];
  if ((tid & 31) == 0) sh[tid >> 5] = s;
  __syncthreads();
  if (tid == 0) {
    float tot = 0.f;
    #pragma unroll
    for (int w = 0; w < 8; w++) tot += sh[w];
    out[z] = tot / (float)NR;
  }
}

// ---------------- launch ----------------
extern "C" void kernel_launch(void* const* d_in, const int* in_sizes, int n_in,
                              void* d_out, int out_size) {
  const int*   label  = (const int*)d_in[0];
  const float* colorf = (const float*)d_in[1];
  const float* otherf = (const float*)d_in[2];
  float* out = (float*)d_out;

  k_zero<<<1, 64>>>();
#if RNG_SCHEME == 2
  k_keys<<<(HW_ + 255) / 256, 256>>>(label);
#else
  k_keys<<<(2 * HW_ + 255) / 256, 256>>>(label);
#endif
  k_select<<<NT, 256>>>(label);
  k_gather<<<dim3(NR, 2), 256>>>(colorf, otherf);
  k_gemm<<<dim3(30, 30, 3), 256>>>();
  k_loss<<<dim3(NR, 3), 128>>>();
  k_final<<<3, 256>>>(out);
}

// round 7
// speedup vs baseline: 1.2922x; 1.2922x over previous
#include <cuda_runtime.h>
#include <cuda_bf16.h>
#include <stdint.h>
#include <math.h>

// ---------------- problem constants ----------------
#define HW_    32768
#define NCLS_  19
#define NVIEW  50
#define NT     38
#define NR     1900
#define NCH    256
#define KX     768          // split-GEMM K: [hi|lo|hi] x [hi|hi|lo]

// ---------------- scratch ----------------
__device__ unsigned long long g_list[(size_t)NT * HW_];
__device__ int   g_cnt[NT];
__device__ int   g_sel[NT * NVIEW];
__device__ float g_feat[2][NR * NCH];                    // fp32 (for k_loss positives)
__device__ __nv_bfloat16 g_gA[2][(size_t)NR * KX];       // A-side: [hi | lo | hi]
__device__ __nv_bfloat16 g_gB[2][(size_t)NR * KX];       // B-side: [hi | hi | lo]
__device__ float g_Spart[3][NR * 16];                    // 15 col-tiles of 128
__device__ float g_classloss[3 * NCLS_];

__device__ __constant__ int c_AS[3] = {0, 0, 1};
__device__ __constant__ int c_BS[3] = {1, 0, 1};

// ---------------- threefry2x32, key (0, 42) ----------------
__device__ __forceinline__ void threefry2x32(uint32_t c0, uint32_t c1,
                                             uint32_t &o0, uint32_t &o1) {
  const uint32_t ks0 = 0u, ks1 = 42u;
  const uint32_t ks2 = 0u ^ 42u ^ 0x1BD11BDAu;
  uint32_t x0 = c0 + ks0, x1 = c1 + ks1;
#define TFR(r) { x0 += x1; x1 = (x1 << (r)) | (x1 >> (32 - (r))); x1 ^= x0; }
  TFR(13) TFR(15) TFR(26) TFR(6)
  x0 += ks1; x1 += ks2 + 1u;
  TFR(17) TFR(29) TFR(16) TFR(24)
  x0 += ks2; x1 += ks0 + 2u;
  TFR(13) TFR(15) TFR(26) TFR(6)
  x0 += ks0; x1 += ks1 + 3u;
  TFR(17) TFR(29) TFR(16) TFR(24)
  x0 += ks1; x1 += ks2 + 4u;
  TFR(13) TFR(15) TFR(26) TFR(6)
  x0 += ks2; x1 += ks0 + 5u;
#undef TFR
  o0 = x0; o1 = x1;
}

__device__ __forceinline__ uint32_t smem_u32(const void* p) {
  uint32_t a;
  asm("{ .reg .u64 t; cvta.to.shared.u64 t, %1; cvt.u32.u64 %0, t; }" : "=r"(a) : "l"(p));
  return a;
}

// ---------------- K0 ----------------
__global__ void k_zero() {
  if (threadIdx.x < NT) g_cnt[threadIdx.x] = 0;
}

// ---------------- K1: keys + hierarchical per-class compaction ----------------
__global__ __launch_bounds__(256) void k_keys(const int* __restrict__ label) {
  __shared__ int scnt[NT], sbase[NT];
  int tid = threadIdx.x;
  if (tid < NT) scnt[tid] = 0;
  __syncthreads();
  int hw = blockIdx.x * 256 + tid;
  uint32_t o0, o1;
  threefry2x32((uint32_t)hw, (uint32_t)(hw + HW_), o0, o1);
  int l0 = label[(hw >> 8) * 4096 + (hw & 255) * 4];
  int l1 = label[524288 + (hw >> 8) * 4096 + (hw & 255) * 4];
  int t0 = l0, t1 = NCLS_ + l1;
  unsigned long long k0 = ((unsigned long long)(o0 >> 9) << 32) | (unsigned)hw;
  unsigned long long k1 = ((unsigned long long)(o1 >> 9) << 32) | (unsigned)hw;
  int r0 = atomicAdd(&scnt[t0], 1);
  int r1 = atomicAdd(&scnt[t1], 1);
  __syncthreads();
  if (tid < NT && scnt[tid] > 0) sbase[tid] = atomicAdd(&g_cnt[tid], scnt[tid]);
  __syncthreads();
  g_list[(size_t)t0 * HW_ + sbase[t0] + r0] = k0;
  g_list[(size_t)t1 * HW_ + sbase[t1] + r1] = k1;
}

// ---------------- K2: histogram top-50 select ----------------
__global__ __launch_bounds__(256) void k_select(const int* __restrict__ label) {
  int t = blockIdx.x, tid = threadIdx.x;
  int cnt = g_cnt[t];
  int lim = min(cnt, NVIEW);
  const unsigned long long* lst = &g_list[(size_t)t * HW_];
  __shared__ int hist[256];
  __shared__ unsigned long long cand[256];
  __shared__ int ncand, nsel, sbin, sneed;
  hist[tid] = 0;
  if (tid == 0) { ncand = 0; nsel = 0; }
  __syncthreads();
  for (int i = tid; i < cnt; i += 256) atomicAdd(&hist[(int)(lst[i] >> 47)], 1);
  __syncthreads();
  if (tid == 0) {
    int cum = 0, b = 0;
    for (; b < 256; b++) { if (cum + hist[b] >= lim) break; cum += hist[b]; }
    sbin = b; sneed = lim - cum;
  }
  __syncthreads();
  int B = sbin;
  for (int i = tid; i < cnt; i += 256) {
    unsigned long long k = lst[i];
    int b = (int)(k >> 47);
    if (b < B) { int p = atomicAdd(&nsel, 1); g_sel[t * NVIEW + p] = (int)(k & 0xffffffffu); }
    else if (b == B) { int p = atomicAdd(&ncand, 1); if (p < 256) cand[p] = k; }
  }
  __syncthreads();
  if (tid == 0) {
    int base = nsel, nc = min(ncand, 256), need = sneed;
    for (int r = 0; r < need; r++) {
      unsigned long long best = ~0ull; int qb = -1;
      for (int q = 0; q < nc; q++) { unsigned long long k = cand[q]; if (k < best) { best = k; qb = q; } }
      cand[qb] = ~0ull;
      g_sel[t * NVIEW + base + r] = (int)(best & 0xffffffffu);
    }
    if (cnt < NVIEW) {
      int n = t / NCLS_, cls = t % NCLS_, fill = cnt;
      for (int hw = 0; hw < HW_ && fill < NVIEW; hw++) {
        int lbl = label[n * 524288 + (hw >> 8) * 4096 + (hw & 255) * 4];
        if (lbl != cls) g_sel[t * NVIEW + fill++] = hw;
      }
    }
  }
}

// ---------------- K3: gather + normalize + hi/lo bf16 precompute ----------------
__global__ __launch_bounds__(256) void k_gather(const float* __restrict__ colorf,
                                                const float* __restrict__ otherf) {
  int row = blockIdx.x, mod = blockIdx.y;
  int t = row / NVIEW, v = row % NVIEW, n = t / NCLS_;
  int p = g_sel[t * NVIEW + v];
  const float* f = mod ? otherf : colorf;
  int ch = threadIdx.x;
  float val = f[((size_t)n * NCH + ch) * HW_ + p];
  float sq = val * val;
  #pragma unroll
  for (int o = 16; o; o >>= 1) sq += __shfl_xor_sync(0xffffffffu, sq, o);
  __shared__ float ws[8];
  if ((ch & 31) == 0) ws[ch >> 5] = sq;
  __syncthreads();
  __shared__ float s_inv;
  if (ch == 0) {
    float s = 0.f;
    #pragma unroll
    for (int i = 0; i < 8; i++) s += ws[i];
    s_inv = 1.0f / fmaxf(sqrtf(s), 1e-12f);
  }
  __syncthreads();
  float nv = val * s_inv;
  g_feat[mod][row * NCH + ch] = nv;
  __nv_bfloat16 hi = __float2bfloat16(nv);
  __nv_bfloat16 lo = __float2bfloat16(nv - __bfloat162float(hi));
  __nv_bfloat16* gA = &g_gA[mod][(size_t)row * KX];
  __nv_bfloat16* gB = &g_gB[mod][(size_t)row * KX];
  gA[ch] = hi;  gA[256 + ch] = lo;  gA[512 + ch] = hi;
  gB[ch] = hi;  gB[256 + ch] = hi;  gB[512 + ch] = lo;
}

// ---------------- K4: mma.sync bf16 GEMM (K=768) + fused S_neg epilogue ----------------
#define SM_AS(st)  ((st) * 16384)
#define SM_BS(st)  (32768 + (st) * 16384)
#define SM_SPART   65536
#define SM_CLSR    67584
#define SM_CLSC    68096
#define GEMM_SMEM  68608
#define NCHUNK     12

__device__ __forceinline__ void ld_stage(uint32_t sA, uint32_t sB,
                                         const __nv_bfloat16* __restrict__ gAp,
                                         const __nv_bfloat16* __restrict__ gBp,
                                         int i0, int j0, int k0) {
  int tid = threadIdx.x;
  #pragma unroll
  for (int e = 0; e < 4; e++) {
    int idx = tid + e * 256;               // 0..1023 -> 128 rows x 8 groups of 16B
    int row = idx >> 3, g = idx & 7;
    uint32_t soff = row * 128 + ((g * 16) ^ ((row & 7) << 4));
    int ra = min(i0 + row, NR - 1);
    int sza = (i0 + row < NR) ? 16 : 0;
    const void* srcA = gAp + (size_t)ra * KX + k0 + g * 8;
    asm volatile("cp.async.cg.shared.global [%0], [%1], 16, %2;"
                 :: "r"(sA + soff), "l"(srcA), "r"(sza));
    int rb = min(j0 + row, NR - 1);
    int szb = (j0 + row < NR) ? 16 : 0;
    const void* srcB = gBp + (size_t)rb * KX + k0 + g * 8;
    asm volatile("cp.async.cg.shared.global [%0], [%1], 16, %2;"
                 :: "r"(sB + soff), "l"(srcB), "r"(szb));
  }
  asm volatile("cp.async.commit_group;" ::: "memory");
}

__global__ __launch_bounds__(256, 2) void k_gemm() {
  extern __shared__ __align__(128) char sm[];
  uint32_t sb = smem_u32(sm);
  int tid = threadIdx.x, lane = tid & 31, wid = tid >> 5;
  int wr = wid >> 2, wc = wid & 3;         // 2 x 4 warp grid; warp tile 64 x 32
  int bx = blockIdx.x, by = blockIdx.y, z = blockIdx.z;
  int i0 = by * 128, j0 = bx * 128;
  const __nv_bfloat16* __restrict__ Ag = g_gA[c_AS[z]];
  const __nv_bfloat16* __restrict__ Bg = g_gB[c_BS[z]];

  // class tables
  if (tid < 128) {
    int gi = i0 + tid, gj = j0 + tid;
    ((int*)(sm + SM_CLSR))[tid] = (gi < NR) ? (gi / NVIEW) % NCLS_ : -2;
    ((int*)(sm + SM_CLSC))[tid] = (gj < NR) ? (gj / NVIEW) % NCLS_ : -1;
  }

  float acc[4][4][4];
  #pragma unroll
  for (int a = 0; a < 4; a++)
    #pragma unroll
    for (int b = 0; b < 4; b++)
      #pragma unroll
      for (int c = 0; c < 4; c++) acc[a][b][c] = 0.f;

  ld_stage(sb + SM_AS(0), sb + SM_BS(0), Ag, Bg, i0, j0, 0);

  #pragma unroll 1
  for (int ch = 0; ch < NCHUNK; ch++) {
    __syncthreads();   // prior compute on the buffer being overwritten is done
    if (ch + 1 < NCHUNK) {
      ld_stage(sb + SM_AS((ch + 1) & 1), sb + SM_BS((ch + 1) & 1), Ag, Bg, i0, j0, (ch + 1) * 64);
      asm volatile("cp.async.wait_group 1;" ::: "memory");
    } else {
      asm volatile("cp.async.wait_group 0;" ::: "memory");
    }
    __syncthreads();
    uint32_t sA = sb + SM_AS(ch & 1), sB = sb + SM_BS(ch & 1);

    #pragma unroll
    for (int ks = 0; ks < 4; ks++) {
      uint32_t af[4][4], bf[2][4];
      #pragma unroll
      for (int mt = 0; mt < 4; mt++) {
        int r = wr * 64 + mt * 16 + (lane & 15);
        uint32_t addr = sA + r * 128 + ((ks * 32 + (lane >> 4) * 16) ^ ((r & 7) << 4));
        asm volatile("ldmatrix.sync.aligned.m8n8.x4.shared.b16 {%0,%1,%2,%3}, [%4];"
                     : "=r"(af[mt][0]), "=r"(af[mt][1]), "=r"(af[mt][2]), "=r"(af[mt][3])
                     : "r"(addr));
      }
      #pragma unroll
      for (int np = 0; np < 2; np++) {
        int n = wc * 32 + np * 16 + (lane & 15);
        uint32_t addr = sB + n * 128 + ((ks * 32 + (lane >> 4) * 16) ^ ((n & 7) << 4));
        asm volatile("ldmatrix.sync.aligned.m8n8.x4.shared.b16 {%0,%1,%2,%3}, [%4];"
                     : "=r"(bf[np][0]), "=r"(bf[np][1]), "=r"(bf[np][2]), "=r"(bf[np][3])
                     : "r"(addr));
      }
      #pragma unroll
      for (int mt = 0; mt < 4; mt++)
        #pragma unroll
        for (int nt = 0; nt < 4; nt++) {
          uint32_t b0 = bf[nt >> 1][nt & 1], b1 = bf[nt >> 1][(nt & 1) + 2];
          asm volatile("mma.sync.aligned.m16n8k16.row.col.f32.bf16.bf16.f32 "
                       "{%0,%1,%2,%3}, {%4,%5,%6,%7}, {%8,%9}, {%0,%1,%2,%3};"
                       : "+f"(acc[mt][nt][0]), "+f"(acc[mt][nt][1]),
                         "+f"(acc[mt][nt][2]), "+f"(acc[mt][nt][3])
                       : "r"(af[mt][0]), "r"(af[mt][1]), "r"(af[mt][2]), "r"(af[mt][3]),
                         "r"(b0), "r"(b1));
        }
    }
  }

  // ---- epilogue: S_neg per row ----
  __syncthreads();
  const int* clsR = (const int*)(sm + SM_CLSR);
  const int* clsC = (const int*)(sm + SM_CLSC);
  float* spart = (float*)(sm + SM_SPART);
  #pragma unroll
  for (int mt = 0; mt < 4; mt++) {
    int rl = wr * 64 + mt * 16 + (lane >> 2);
    int cr0 = clsR[rl], cr1 = clsR[rl + 8];
    float es0 = 0.f, es1 = 0.f;
    #pragma unroll
    for (int nt = 0; nt < 4; nt++) {
      int cl = wc * 32 + nt * 8 + (lane & 3) * 2;
      int cc0 = clsC[cl], cc1 = clsC[cl + 1];
      if (cc0 >= 0) {
        if (cc0 != cr0) es0 += __expf(acc[mt][nt][0] * 10.0f);
        if (cc0 != cr1) es1 += __expf(acc[mt][nt][2] * 10.0f);
      }
      if (cc1 >= 0) {
        if (cc1 != cr0) es0 += __expf(acc[mt][nt][1] * 10.0f);
        if (cc1 != cr1) es1 += __expf(acc[mt][nt][3] * 10.0f);
      }
    }
    es0 += __shfl_xor_sync(0xffffffffu, es0, 1);
    es0 += __shfl_xor_sync(0xffffffffu, es0, 2);
    es1 += __shfl_xor_sync(0xffffffffu, es1, 1);
    es1 += __shfl_xor_sync(0xffffffffu, es1, 2);
    if ((lane & 3) == 0) {
      spart[wc * 128 + rl] = es0;
      spart[wc * 128 + rl + 8] = es1;
    }
  }
  __syncthreads();
  if (tid < 128) {
    int gi = i0 + tid;
    if (gi < NR) {
      float s = spart[tid] + spart[128 + tid] + spart[256 + tid] + spart[384 + tid];
      g_Spart[z][gi * 16 + bx] = s;
    }
  }
}

// ---------------- K5: per-class positive block + InfoNCE (fp32 exact) ----------------
__device__ __forceinline__ int gRow(int ci, int r) {
  return (r < NVIEW) ? ci * NVIEW + r : (NR / 2) + ci * NVIEW + (r - NVIEW);
}

__global__ __launch_bounds__(256) void k_loss() {
  int ci = blockIdx.x, z = blockIdx.y;
  const float* __restrict__ A = g_feat[c_AS[z]];
  const float* __restrict__ B = g_feat[c_BS[z]];
  __shared__ float As[112][33], Bs[112][33];
  __shared__ float Sneg[112], part[100][16], rl[100];
  int tid = threadIdx.x, tx = tid & 15, ty = tid >> 4;

  if (tid < 100) {
    int gi = gRow(ci, tid);
    float s = 0.f;
    #pragma unroll
    for (int c = 0; c < 15; c++) s += g_Spart[z][gi * 16 + c];
    Sneg[tid] = s;
  }

  float acc[7][7];
  #pragma unroll
  for (int u = 0; u < 7; u++)
    #pragma unroll
    for (int v = 0; v < 7; v++) acc[u][v] = 0.f;

  #pragma unroll 1
  for (int k0 = 0; k0 < NCH; k0 += 32) {
    __syncthreads();
    for (int idx = tid; idx < 112 * 32; idx += 256) {
      int r = idx >> 5, c = idx & 31;
      float av = 0.f, bv = 0.f;
      if (r < 100) {
        int g = gRow(ci, r);
        av = A[g * NCH + k0 + c];
        bv = B[g * NCH + k0 + c];
      }
      As[r][c] = av;
      Bs[r][c] = bv;
    }
    __syncthreads();
    #pragma unroll
    for (int kk = 0; kk < 32; kk++) {
      float av[7], bv[7];
      #pragma unroll
      for (int u = 0; u < 7; u++) av[u] = As[ty * 7 + u][kk];
      #pragma unroll
      for (int v = 0; v < 7; v++) bv[v] = Bs[tx * 7 + v][kk];
      #pragma unroll
      for (int u = 0; u < 7; u++)
        #pragma unroll
        for (int v = 0; v < 7; v++) acc[u][v] = fmaf(av[u], bv[v], acc[u][v]);
    }
  }
  __syncthreads();
  #pragma unroll
  for (int u = 0; u < 7; u++) {
    int i = ty * 7 + u;
    if (i < 100) {
      float sn = Sneg[i];
      float ps = 0.f;
      #pragma unroll
      for (int v = 0; v < 7; v++) {
        int j = tx * 7 + v;
        if (j < 100 && j != i) {
          float d10 = acc[u][v] * 10.0f;
          ps += d10 - logf(expf(d10) + sn);
        }
      }
      part[i][tx] = ps;
    }
  }
  __syncthreads();
  if (tid < 100) {
    float s = 0.f;
    #pragma unroll
    for (int c = 0; c < 16; c++) s += part[tid][c];
    rl[tid] = s;
  }
  __syncthreads();
  if (tid == 0) {
    float tot = 0.f;
    for (int i = 0; i < 100; i++) tot += rl[i];
    g_classloss[z * NCLS_ + ci] = -tot / 99.0f;
  }
}

// ---------------- K6: final ----------------
__global__ void k_final(float* __restrict__ out) {
  int tid = threadIdx.x;
  if (tid < 3) {
    float s = 0.f;
    for (int c = 0; c < NCLS_; c++) s += g_classloss[tid * NCLS_ + c];
    out[tid] = s / (float)NR;
  }
}

// ---------------- launch ----------------
extern "C" void kernel_launch(void* const* d_in, const int* in_sizes, int n_in,
                              void* d_out, int out_size) {
  const int*   label  = (const int*)d_in[0];
  const float* colorf = (const float*)d_in[1];
  const float* otherf = (const float*)d_in[2];
  float* out = (float*)d_out;

  cudaFuncSetAttribute(k_gemm, cudaFuncAttributeMaxDynamicSharedMemorySize, GEMM_SMEM);

  k_zero<<<1, 64>>>();
  k_keys<<<HW_ / 256, 256>>>(label);
  k_select<<<NT, 256>>>(label);
  k_gather<<<dim3(NR, 2), 256>>>(colorf, otherf);
  k_gemm<<<dim3(15, 15, 3), 256, GEMM_SMEM>>>();
  k_loss<<<dim3(NCLS_, 3), 256>>>();
  k_final<<<1, 32>>>(out);
}

// round 8
// speedup vs baseline: 2.0505x; 1.5868x over previous
#include <cuda_runtime.h>
#include <cuda_bf16.h>
#include <stdint.h>
#include <math.h>

// ---------------- problem constants ----------------
#define HW_    32768
#define NCLS_  19
#define NVIEW  50
#define NT     38
#define NR     1900
#define NCH    256
#define KX2    512          // [hi | lo] per row

// ---------------- scratch ----------------
__device__ unsigned long long g_list[(size_t)NT * HW_];
__device__ int   g_cnt[NT];
__device__ int   g_sel[NT * NVIEW];
__device__ __nv_bfloat16 g_g[2][(size_t)NR * KX2];   // [hi(256) | lo(256)] per row per modality
__device__ float g_Spart[3][NR * 16];                // 15 slots of 128-col tiles
__device__ float g_classloss[3 * NCLS_];

__device__ __constant__ int c_AS[3] = {0, 0, 1};
__device__ __constant__ int c_BS[3] = {1, 0, 1};

// ---------------- threefry2x32, key (0, 42) ----------------
__device__ __forceinline__ void threefry2x32(uint32_t c0, uint32_t c1,
                                             uint32_t &o0, uint32_t &o1) {
  const uint32_t ks0 = 0u, ks1 = 42u;
  const uint32_t ks2 = 0u ^ 42u ^ 0x1BD11BDAu;
  uint32_t x0 = c0 + ks0, x1 = c1 + ks1;
#define TFR(r) { x0 += x1; x1 = (x1 << (r)) | (x1 >> (32 - (r))); x1 ^= x0; }
  TFR(13) TFR(15) TFR(26) TFR(6)
  x0 += ks1; x1 += ks2 + 1u;
  TFR(17) TFR(29) TFR(16) TFR(24)
  x0 += ks2; x1 += ks0 + 2u;
  TFR(13) TFR(15) TFR(26) TFR(6)
  x0 += ks0; x1 += ks1 + 3u;
  TFR(17) TFR(29) TFR(16) TFR(24)
  x0 += ks1; x1 += ks2 + 4u;
  TFR(13) TFR(15) TFR(26) TFR(6)
  x0 += ks2; x1 += ks0 + 5u;
#undef TFR
  o0 = x0; o1 = x1;
}

__device__ __forceinline__ uint32_t smem_u32(const void* p) {
  uint32_t a;
  asm("{ .reg .u64 t; cvta.to.shared.u64 t, %1; cvt.u32.u64 %0, t; }" : "=r"(a) : "l"(p));
  return a;
}

// ---------------- K0 ----------------
__global__ void k_zero() {
  if (threadIdx.x < NT) g_cnt[threadIdx.x] = 0;
}

// ---------------- K1: keys + hierarchical per-class compaction ----------------
__global__ __launch_bounds__(256) void k_keys(const int* __restrict__ label) {
  __shared__ int scnt[NT], sbase[NT];
  int tid = threadIdx.x;
  if (tid < NT) scnt[tid] = 0;
  __syncthreads();
  int hw = blockIdx.x * 256 + tid;
  uint32_t o0, o1;
  threefry2x32((uint32_t)hw, (uint32_t)(hw + HW_), o0, o1);
  int l0 = label[(hw >> 8) * 4096 + (hw & 255) * 4];
  int l1 = label[524288 + (hw >> 8) * 4096 + (hw & 255) * 4];
  int t0 = l0, t1 = NCLS_ + l1;
  unsigned long long k0 = ((unsigned long long)(o0 >> 9) << 32) | (unsigned)hw;
  unsigned long long k1 = ((unsigned long long)(o1 >> 9) << 32) | (unsigned)hw;
  int r0 = atomicAdd(&scnt[t0], 1);
  int r1 = atomicAdd(&scnt[t1], 1);
  __syncthreads();
  if (tid < NT && scnt[tid] > 0) sbase[tid] = atomicAdd(&g_cnt[tid], scnt[tid]);
  __syncthreads();
  g_list[(size_t)t0 * HW_ + sbase[t0] + r0] = k0;
  g_list[(size_t)t1 * HW_ + sbase[t1] + r1] = k1;
}

// ---------------- K2: histogram top-50 select ----------------
__global__ __launch_bounds__(256) void k_select(const int* __restrict__ label) {
  int t = blockIdx.x, tid = threadIdx.x;
  int cnt = g_cnt[t];
  int lim = min(cnt, NVIEW);
  const unsigned long long* lst = &g_list[(size_t)t * HW_];
  __shared__ int hist[256];
  __shared__ unsigned long long cand[256];
  __shared__ int ncand, nsel, sbin, sneed;
  hist[tid] = 0;
  if (tid == 0) { ncand = 0; nsel = 0; }
  __syncthreads();
  for (int i = tid; i < cnt; i += 256) atomicAdd(&hist[(int)(lst[i] >> 47)], 1);
  __syncthreads();
  if (tid == 0) {
    int cum = 0, b = 0;
    for (; b < 256; b++) { if (cum + hist[b] >= lim) break; cum += hist[b]; }
    sbin = b; sneed = lim - cum;
  }
  __syncthreads();
  int B = sbin;
  for (int i = tid; i < cnt; i += 256) {
    unsigned long long k = lst[i];
    int b = (int)(k >> 47);
    if (b < B) { int p = atomicAdd(&nsel, 1); g_sel[t * NVIEW + p] = (int)(k & 0xffffffffu); }
    else if (b == B) { int p = atomicAdd(&ncand, 1); if (p < 256) cand[p] = k; }
  }
  __syncthreads();
  if (tid == 0) {
    int base = nsel, nc = min(ncand, 256), need = sneed;
    for (int r = 0; r < need; r++) {
      unsigned long long best = ~0ull; int qb = -1;
      for (int q = 0; q < nc; q++) { unsigned long long k = cand[q]; if (k < best) { best = k; qb = q; } }
      cand[qb] = ~0ull;
      g_sel[t * NVIEW + base + r] = (int)(best & 0xffffffffu);
    }
    if (cnt < NVIEW) {
      int n = t / NCLS_, cls = t % NCLS_, fill = cnt;
      for (int hw = 0; hw < HW_ && fill < NVIEW; hw++) {
        int lbl = label[n * 524288 + (hw >> 8) * 4096 + (hw & 255) * 4];
        if (lbl != cls) g_sel[t * NVIEW + fill++] = hw;
      }
    }
  }
}

// ---------------- K3: gather + normalize + hi/lo bf16 ----------------
__global__ __launch_bounds__(256) void k_gather(const float* __restrict__ colorf,
                                                const float* __restrict__ otherf) {
  int row = blockIdx.x, mod = blockIdx.y;
  int t = row / NVIEW, v = row % NVIEW, n = t / NCLS_;
  int p = g_sel[t * NVIEW + v];
  const float* f = mod ? otherf : colorf;
  int ch = threadIdx.x;
  float val = f[((size_t)n * NCH + ch) * HW_ + p];
  float sq = val * val;
  #pragma unroll
  for (int o = 16; o; o >>= 1) sq += __shfl_xor_sync(0xffffffffu, sq, o);
  __shared__ float ws[8];
  if ((ch & 31) == 0) ws[ch >> 5] = sq;
  __syncthreads();
  __shared__ float s_inv;
  if (ch == 0) {
    float s = 0.f;
    #pragma unroll
    for (int i = 0; i < 8; i++) s += ws[i];
    s_inv = 1.0f / fmaxf(sqrtf(s), 1e-12f);
  }
  __syncthreads();
  float nv = val * s_inv;
  __nv_bfloat16 hi = __float2bfloat16(nv);
  __nv_bfloat16 lo = __float2bfloat16(nv - __bfloat162float(hi));
  __nv_bfloat16* g = &g_g[mod][(size_t)row * KX2];
  g[ch] = hi;
  g[256 + ch] = lo;
}

// ---------------- K4: mma.sync bf16 split GEMM + fused row/col S_neg epilogue ----------------
// 465 tiles: z0 full 15x15; z1,z2 upper triangle (by<=bx), col-sums supply transpose rows.
#define SM_AS(st)  ((st) * 16384)
#define SM_BS(st)  (32768 + (st) * 16384)
#define SM_SPART   65536             // 512 f32 row partials
#define SM_CPART   67584             // 256 f32 col partials
#define SM_CLSR    68608             // 128 i32
#define SM_CLSC    69120             // 128 i32
#define GEMM_SMEM  69632
#define NCHUNK     12
#define NTILES     465

__device__ __forceinline__ void ld_stage(uint32_t sA, uint32_t sB,
                                         const __nv_bfloat16* __restrict__ gAp,
                                         const __nv_bfloat16* __restrict__ gBp,
                                         int i0, int j0, int ch) {
  int tid = threadIdx.x;
  int kA = ((ch & 4) ? 256 : 0) + (ch & 3) * 64;
  int kB = ((ch & 8) ? 256 : 0) + (ch & 3) * 64;
  #pragma unroll
  for (int e = 0; e < 4; e++) {
    int idx = tid + e * 256;               // 128 rows x 8 groups of 16B
    int row = idx >> 3, g = idx & 7;
    uint32_t soff = row * 128 + ((g * 16) ^ ((row & 7) << 4));
    int ra = min(i0 + row, NR - 1);
    int sza = (i0 + row < NR) ? 16 : 0;
    const void* srcA = gAp + (size_t)ra * KX2 + kA + g * 8;
    asm volatile("cp.async.cg.shared.global [%0], [%1], 16, %2;"
                 :: "r"(sA + soff), "l"(srcA), "r"(sza));
    int rb = min(j0 + row, NR - 1);
    int szb = (j0 + row < NR) ? 16 : 0;
    const void* srcB = gBp + (size_t)rb * KX2 + kB + g * 8;
    asm volatile("cp.async.cg.shared.global [%0], [%1], 16, %2;"
                 :: "r"(sB + soff), "l"(srcB), "r"(szb));
  }
  asm volatile("cp.async.commit_group;" ::: "memory");
}

__global__ __launch_bounds__(256, 2) void k_gemm() {
  extern __shared__ __align__(128) char sm[];
  uint32_t sb = smem_u32(sm);
  int tid = threadIdx.x, lane = tid & 31, wid = tid >> 5;
  int wr = wid >> 2, wc = wid & 3;         // 2 x 4 warp grid; warp tile 64 x 32

  // ---- tile decode ----
  int t = blockIdx.x, z, by, bx;
  if (t < 225) { z = 0; by = t / 15; bx = t % 15; }
  else {
    int u = t - 225;
    z = 1 + u / 120;
    int v = u % 120;
    by = 0;
    while (v >= 15 - by) { v -= 15 - by; by++; }
    bx = by + v;
  }
  bool offdiag = (z != 0) && (bx != by);
  int i0 = by * 128, j0 = bx * 128;
  const __nv_bfloat16* __restrict__ Ag = g_g[c_AS[z]];
  const __nv_bfloat16* __restrict__ Bg = g_g[c_BS[z]];

  if (tid < 128) {
    int gi = i0 + tid, gj = j0 + tid;
    ((int*)(sm + SM_CLSR))[tid] = (gi < NR) ? (gi / NVIEW) % NCLS_ : -2;
    ((int*)(sm + SM_CLSC))[tid] = (gj < NR) ? (gj / NVIEW) % NCLS_ : -1;
  }

  float acc[4][4][4];
  #pragma unroll
  for (int a = 0; a < 4; a++)
    #pragma unroll
    for (int b = 0; b < 4; b++)
      #pragma unroll
      for (int c = 0; c < 4; c++) acc[a][b][c] = 0.f;

  ld_stage(sb + SM_AS(0), sb + SM_BS(0), Ag, Bg, i0, j0, 0);

  #pragma unroll 1
  for (int ch = 0; ch < NCHUNK; ch++) {
    __syncthreads();
    if (ch + 1 < NCHUNK) {
      ld_stage(sb + SM_AS((ch + 1) & 1), sb + SM_BS((ch + 1) & 1), Ag, Bg, i0, j0, ch + 1);
      asm volatile("cp.async.wait_group 1;" ::: "memory");
    } else {
      asm volatile("cp.async.wait_group 0;" ::: "memory");
    }
    __syncthreads();
    uint32_t sA = sb + SM_AS(ch & 1), sB = sb + SM_BS(ch & 1);

    #pragma unroll
    for (int ks = 0; ks < 4; ks++) {
      uint32_t af[4][4], bf[2][4];
      #pragma unroll
      for (int mt = 0; mt < 4; mt++) {
        int r = wr * 64 + mt * 16 + (lane & 15);
        uint32_t addr = sA + r * 128 + ((ks * 32 + (lane >> 4) * 16) ^ ((r & 7) << 4));
        asm volatile("ldmatrix.sync.aligned.m8n8.x4.shared.b16 {%0,%1,%2,%3}, [%4];"
                     : "=r"(af[mt][0]), "=r"(af[mt][1]), "=r"(af[mt][2]), "=r"(af[mt][3])
                     : "r"(addr));
      }
      #pragma unroll
      for (int np = 0; np < 2; np++) {
        int n = wc * 32 + np * 16 + (lane & 15);
        uint32_t addr = sB + n * 128 + ((ks * 32 + (lane >> 4) * 16) ^ ((n & 7) << 4));
        asm volatile("ldmatrix.sync.aligned.m8n8.x4.shared.b16 {%0,%1,%2,%3}, [%4];"
                     : "=r"(bf[np][0]), "=r"(bf[np][1]), "=r"(bf[np][2]), "=r"(bf[np][3])
                     : "r"(addr));
      }
      #pragma unroll
      for (int mt = 0; mt < 4; mt++)
        #pragma unroll
        for (int nt = 0; nt < 4; nt++) {
          uint32_t b0 = bf[nt >> 1][nt & 1], b1 = bf[nt >> 1][(nt & 1) + 2];
          asm volatile("mma.sync.aligned.m16n8k16.row.col.f32.bf16.bf16.f32 "
                       "{%0,%1,%2,%3}, {%4,%5,%6,%7}, {%8,%9}, {%0,%1,%2,%3};"
                       : "+f"(acc[mt][nt][0]), "+f"(acc[mt][nt][1]),
                         "+f"(acc[mt][nt][2]), "+f"(acc[mt][nt][3])
                       : "r"(af[mt][0]), "r"(af[mt][1]), "r"(af[mt][2]), "r"(af[mt][3]),
                         "r"(b0), "r"(b1));
        }
    }
  }

  // ---- epilogue: masked exp; row sums always, col sums for symmetric off-diagonal ----
  __syncthreads();
  const int* clsR = (const int*)(sm + SM_CLSR);
  const int* clsC = (const int*)(sm + SM_CLSC);
  float* spart = (float*)(sm + SM_SPART);
  float* cpart = (float*)(sm + SM_CPART);

  float ec[4][2];
  #pragma unroll
  for (int nt = 0; nt < 4; nt++) { ec[nt][0] = 0.f; ec[nt][1] = 0.f; }

  #pragma unroll
  for (int mt = 0; mt < 4; mt++) {
    int rl = wr * 64 + mt * 16 + (lane >> 2);
    int cr0 = clsR[rl], cr1 = clsR[rl + 8];
    float es0 = 0.f, es1 = 0.f;
    #pragma unroll
    for (int nt = 0; nt < 4; nt++) {
      int cl = wc * 32 + nt * 8 + (lane & 3) * 2;
      int cc0 = clsC[cl], cc1 = clsC[cl + 1];
      float e00 = (cc0 >= 0 && cr0 >= 0 && cc0 != cr0) ? __expf(acc[mt][nt][0] * 10.0f) : 0.f;
      float e01 = (cc1 >= 0 && cr0 >= 0 && cc1 != cr0) ? __expf(acc[mt][nt][1] * 10.0f) : 0.f;
      float e10 = (cc0 >= 0 && cr1 >= 0 && cc0 != cr1) ? __expf(acc[mt][nt][2] * 10.0f) : 0.f;
      float e11 = (cc1 >= 0 && cr1 >= 0 && cc1 != cr1) ? __expf(acc[mt][nt][3] * 10.0f) : 0.f;
      es0 += e00 + e01;
      es1 += e10 + e11;
      ec[nt][0] += e00 + e10;
      ec[nt][1] += e01 + e11;
    }
    es0 += __shfl_xor_sync(0xffffffffu, es0, 1);
    es0 += __shfl_xor_sync(0xffffffffu, es0, 2);
    es1 += __shfl_xor_sync(0xffffffffu, es1, 1);
    es1 += __shfl_xor_sync(0xffffffffu, es1, 2);
    if ((lane & 3) == 0) {
      spart[wc * 128 + rl] = es0;
      spart[wc * 128 + rl + 8] = es1;
    }
  }
  if (offdiag) {
    #pragma unroll
    for (int nt = 0; nt < 4; nt++) {
      #pragma unroll
      for (int h = 0; h < 2; h++) {
        float v = ec[nt][h];
        v += __shfl_xor_sync(0xffffffffu, v, 4);
        v += __shfl_xor_sync(0xffffffffu, v, 8);
        v += __shfl_xor_sync(0xffffffffu, v, 16);
        if ((lane >> 2) == 0) {
          int cl = wc * 32 + nt * 8 + (lane & 3) * 2 + h;
          cpart[wr * 128 + cl] = v;
        }
      }
    }
  }
  __syncthreads();
  if (tid < 128) {
    int gi = i0 + tid;
    if (gi < NR) {
      float s = spart[tid] + spart[128 + tid] + spart[256 + tid] + spart[384 + tid];
      g_Spart[z][gi * 16 + bx] = s;
    }
    if (offdiag) {
      int gj = j0 + tid;
      if (gj < NR) g_Spart[z][gj * 16 + by] = cpart[tid] + cpart[128 + tid];
    }
  }
}

// ---------------- K5: per-class positive block + InfoNCE (hi+lo reconstructed fp32) ----------------
__device__ __forceinline__ int gRow(int ci, int r) {
  return (r < NVIEW) ? ci * NVIEW + r : (NR / 2) + ci * NVIEW + (r - NVIEW);
}

__global__ __launch_bounds__(256) void k_loss() {
  int ci = blockIdx.x, z = blockIdx.y;
  const __nv_bfloat16* __restrict__ A = g_g[c_AS[z]];
  const __nv_bfloat16* __restrict__ B = g_g[c_BS[z]];
  __shared__ float As[112][33], Bs[112][33];
  __shared__ float Sneg[112], part[100][16], rl[100];
  int tid = threadIdx.x, tx = tid & 15, ty = tid >> 4;

  if (tid < 100) {
    int gi = gRow(ci, tid);
    float s = 0.f;
    #pragma unroll
    for (int c = 0; c < 15; c++) s += g_Spart[z][gi * 16 + c];
    Sneg[tid] = s;
  }

  float acc[7][7];
  #pragma unroll
  for (int u = 0; u < 7; u++)
    #pragma unroll
    for (int v = 0; v < 7; v++) acc[u][v] = 0.f;

  #pragma unroll 1
  for (int k0 = 0; k0 < NCH; k0 += 32) {
    __syncthreads();
    for (int idx = tid; idx < 112 * 32; idx += 256) {
      int r = idx >> 5, c = idx & 31;
      float av = 0.f, bv = 0.f;
      if (r < 100) {
        int g = gRow(ci, r);
        const __nv_bfloat16* ap = &A[(size_t)g * KX2 + k0 + c];
        const __nv_bfloat16* bp = &B[(size_t)g * KX2 + k0 + c];
        av = __bfloat162float(ap[0]) + __bfloat162float(ap[256]);
        bv = __bfloat162float(bp[0]) + __bfloat162float(bp[256]);
      }
      As[r][c] = av;
      Bs[r][c] = bv;
    }
    __syncthreads();
    #pragma unroll
    for (int kk = 0; kk < 32; kk++) {
      float av[7], bv[7];
      #pragma unroll
      for (int u = 0; u < 7; u++) av[u] = As[ty * 7 + u][kk];
      #pragma unroll
      for (int v = 0; v < 7; v++) bv[v] = Bs[tx * 7 + v][kk];
      #pragma unroll
      for (int u = 0; u < 7; u++)
        #pragma unroll
        for (int v = 0; v < 7; v++) acc[u][v] = fmaf(av[u], bv[v], acc[u][v]);
    }
  }
  __syncthreads();
  #pragma unroll
  for (int u = 0; u < 7; u++) {
    int i = ty * 7 + u;
    if (i < 100) {
      float sn = Sneg[i];
      float ps = 0.f;
      #pragma unroll
      for (int v = 0; v < 7; v++) {
        int j = tx * 7 + v;
        if (j < 100 && j != i) {
          float d10 = acc[u][v] * 10.0f;
          ps += d10 - logf(expf(d10) + sn);
        }
      }
      part[i][tx] = ps;
    }
  }
  __syncthreads();
  if (tid < 100) {
    float s = 0.f;
    #pragma unroll
    for (int c = 0; c < 16; c++) s += part[tid][c];
    rl[tid] = s;
  }
  __syncthreads();
  if (tid == 0) {
    float tot = 0.f;
    for (int i = 0; i < 100; i++) tot += rl[i];
    g_classloss[z * NCLS_ + ci] = -tot / 99.0f;
  }
}

// ---------------- K6: final ----------------
__global__ void k_final(float* __restrict__ out) {
  int tid = threadIdx.x;
  if (tid < 3) {
    float s = 0.f;
    for (int c = 0; c < NCLS_; c++) s += g_classloss[tid * NCLS_ + c];
    out[tid] = s / (float)NR;
  }
}

// ---------------- launch ----------------
extern "C" void kernel_launch(void* const* d_in, const int* in_sizes, int n_in,
                              void* d_out, int out_size) {
  const int*   label  = (const int*)d_in[0];
  const float* colorf = (const float*)d_in[1];
  const float* otherf = (const float*)d_in[2];
  float* out = (float*)d_out;

  cudaFuncSetAttribute(k_gemm, cudaFuncAttributeMaxDynamicSharedMemorySize, GEMM_SMEM);

  k_zero<<<1, 64>>>();
  k_keys<<<HW_ / 256, 256>>>(label);
  k_select<<<NT, 256>>>(label);
  k_gather<<<dim3(NR, 2), 256>>>(colorf, otherf);
  k_gemm<<<NTILES, 256, GEMM_SMEM>>>();
  k_loss<<<dim3(NCLS_, 3), 256>>>();
  k_final<<<1, 32>>>(out);
}

// round 10
// speedup vs baseline: 2.4429x; 1.1914x over previous
#include <cuda_runtime.h>
#include <cuda_fp16.h>
#include <stdint.h>
#include <math.h>

// ---------------- problem constants ----------------
#define HW_    32768
#define NCLS_  19
#define NVIEW  50
#define NT     38
#define NR     1900
#define NCH    256
#define KX2    512          // [hi | lo] fp16 per row

// ---------------- scratch ----------------
__device__ unsigned long long g_list[(size_t)NT * HW_];
__device__ int   g_cnt[NT];
__device__ int   g_sel[NT * NVIEW];
__device__ __half g_g[2][(size_t)NR * KX2];          // [hi(256) | lo(256)] per row per modality
__device__ float g_Spart[3][NR * 16];                // 15 slots of 128-col tiles
__device__ float g_classloss[3 * NCLS_];

__device__ __constant__ int c_AS[3] = {0, 0, 1};
__device__ __constant__ int c_BS[3] = {1, 0, 1};

// ---------------- threefry2x32, key (0, 42) ----------------
__device__ __forceinline__ void threefry2x32(uint32_t c0, uint32_t c1,
                                             uint32_t &o0, uint32_t &o1) {
  const uint32_t ks0 = 0u, ks1 = 42u;
  const uint32_t ks2 = 0u ^ 42u ^ 0x1BD11BDAu;
  uint32_t x0 = c0 + ks0, x1 = c1 + ks1;
#define TFR(r) { x0 += x1; x1 = (x1 << (r)) | (x1 >> (32 - (r))); x1 ^= x0; }
  TFR(13) TFR(15) TFR(26) TFR(6)
  x0 += ks1; x1 += ks2 + 1u;
  TFR(17) TFR(29) TFR(16) TFR(24)
  x0 += ks2; x1 += ks0 + 2u;
  TFR(13) TFR(15) TFR(26) TFR(6)
  x0 += ks0; x1 += ks1 + 3u;
  TFR(17) TFR(29) TFR(16) TFR(24)
  x0 += ks1; x1 += ks2 + 4u;
  TFR(13) TFR(15) TFR(26) TFR(6)
  x0 += ks2; x1 += ks0 + 5u;
#undef TFR
  o0 = x0; o1 = x1;
}

__device__ __forceinline__ uint32_t smem_u32(const void* p) {
  uint32_t a;
  asm("{ .reg .u64 t; cvta.to.shared.u64 t, %1; cvt.u32.u64 %0, t; }" : "=r"(a) : "l"(p));
  return a;
}

// ---------------- K0 ----------------
__global__ void k_zero() {
  if (threadIdx.x < NT) g_cnt[threadIdx.x] = 0;
}

// ---------------- K1: keys + hierarchical per-class compaction ----------------
__global__ __launch_bounds__(256) void k_keys(const int* __restrict__ label) {
  __shared__ int scnt[NT], sbase[NT];
  int tid = threadIdx.x;
  if (tid < NT) scnt[tid] = 0;
  __syncthreads();
  int hw = blockIdx.x * 256 + tid;
  uint32_t o0, o1;
  threefry2x32((uint32_t)hw, (uint32_t)(hw + HW_), o0, o1);
  int l0 = label[(hw >> 8) * 4096 + (hw & 255) * 4];
  int l1 = label[524288 + (hw >> 8) * 4096 + (hw & 255) * 4];
  int t0 = l0, t1 = NCLS_ + l1;
  unsigned long long k0 = ((unsigned long long)(o0 >> 9) << 32) | (unsigned)hw;
  unsigned long long k1 = ((unsigned long long)(o1 >> 9) << 32) | (unsigned)hw;
  int r0 = atomicAdd(&scnt[t0], 1);
  int r1 = atomicAdd(&scnt[t1], 1);
  __syncthreads();
  if (tid < NT && scnt[tid] > 0) sbase[tid] = atomicAdd(&g_cnt[tid], scnt[tid]);
  __syncthreads();
  g_list[(size_t)t0 * HW_ + sbase[t0] + r0] = k0;
  g_list[(size_t)t1 * HW_ + sbase[t1] + r1] = k1;
}

// ---------------- K2: histogram top-50 select ----------------
__global__ __launch_bounds__(256) void k_select(const int* __restrict__ label) {
  int t = blockIdx.x, tid = threadIdx.x;
  int cnt = g_cnt[t];
  int lim = min(cnt, NVIEW);
  const unsigned long long* lst = &g_list[(size_t)t * HW_];
  __shared__ int hist[256];
  __shared__ unsigned long long cand[256];
  __shared__ int ncand, nsel, sbin, sneed;
  hist[tid] = 0;
  if (tid == 0) { ncand = 0; nsel = 0; }
  __syncthreads();
  for (int i = tid; i < cnt; i += 256) atomicAdd(&hist[(int)(lst[i] >> 47)], 1);
  __syncthreads();
  if (tid == 0) {
    int cum = 0, b = 0;
    for (; b < 256; b++) { if (cum + hist[b] >= lim) break; cum += hist[b]; }
    sbin = b; sneed = lim - cum;
  }
  __syncthreads();
  int B = sbin;
  for (int i = tid; i < cnt; i += 256) {
    unsigned long long k = lst[i];
    int b = (int)(k >> 47);
    if (b < B) { int p = atomicAdd(&nsel, 1); g_sel[t * NVIEW + p] = (int)(k & 0xffffffffu); }
    else if (b == B) { int p = atomicAdd(&ncand, 1); if (p < 256) cand[p] = k; }
  }
  __syncthreads();
  if (tid == 0) {
    int base = nsel, nc = min(ncand, 256), need = sneed;
    for (int r = 0; r < need; r++) {
      unsigned long long best = ~0ull; int qb = -1;
      for (int q = 0; q < nc; q++) { unsigned long long k = cand[q]; if (k < best) { best = k; qb = q; } }
      cand[qb] = ~0ull;
      g_sel[t * NVIEW + base + r] = (int)(best & 0xffffffffu);
    }
    if (cnt < NVIEW) {
      int n = t / NCLS_, cls = t % NCLS_, fill = cnt;
      for (int hw = 0; hw < HW_ && fill < NVIEW; hw++) {
        int lbl = label[n * 524288 + (hw >> 8) * 4096 + (hw & 255) * 4];
        if (lbl != cls) g_sel[t * NVIEW + fill++] = hw;
      }
    }
  }
}

// ---------------- K3: gather + normalize + hi/lo fp16 ----------------
__global__ __launch_bounds__(256) void k_gather(const float* __restrict__ colorf,
                                                const float* __restrict__ otherf) {
  int row = blockIdx.x, mod = blockIdx.y;
  int t = row / NVIEW, v = row % NVIEW, n = t / NCLS_;
  int p = g_sel[t * NVIEW + v];
  const float* f = mod ? otherf : colorf;
  int ch = threadIdx.x;
  float val = f[((size_t)n * NCH + ch) * HW_ + p];
  float sq = val * val;
  #pragma unroll
  for (int o = 16; o; o >>= 1) sq += __shfl_xor_sync(0xffffffffu, sq, o);
  __shared__ float ws[8];
  if ((ch & 31) == 0) ws[ch >> 5] = sq;
  __syncthreads();
  __shared__ float s_inv;
  if (ch == 0) {
    float s = 0.f;
    #pragma unroll
    for (int i = 0; i < 8; i++) s += ws[i];
    s_inv = 1.0f / fmaxf(sqrtf(s), 1e-12f);
  }
  __syncthreads();
  float nv = val * s_inv;
  __half hi = __float2half(nv);
  __half lo = __float2half(nv - __half2float(hi));
  __half* g = &g_g[mod][(size_t)row * KX2];
  g[ch] = hi;
  g[256 + ch] = lo;
}

// ---------------- K4: mma.sync fp16 GEMM (single hi pass, K=256) + fused S_neg epilogue ----------------
// 465 tiles: z0 full 15x15; z1,z2 upper triangle (by<=bx), col-sums supply transpose rows.
#define SM_AS(st)  ((st) * 16384)
#define SM_BS(st)  (32768 + (st) * 16384)
#define SM_SPART   65536             // 512 f32 row partials
#define SM_CPART   67584             // 256 f32 col partials
#define SM_CLSR    68608             // 128 i32
#define SM_CLSC    69120             // 128 i32
#define GEMM_SMEM  69632
#define NCHUNK     4
#define NTILES     465

__device__ __forceinline__ void ld_stage(uint32_t sA, uint32_t sB,
                                         const __half* __restrict__ gAp,
                                         const __half* __restrict__ gBp,
                                         int i0, int j0, int ch) {
  int tid = threadIdx.x;
  int k0 = ch * 64;                        // hi block only (first 256 halves)
  #pragma unroll
  for (int e = 0; e < 4; e++) {
    int idx = tid + e * 256;               // 128 rows x 8 groups of 16B
    int row = idx >> 3, g = idx & 7;
    uint32_t soff = row * 128 + ((g * 16) ^ ((row & 7) << 4));
    int ra = min(i0 + row, NR - 1);
    int sza = (i0 + row < NR) ? 16 : 0;
    const void* srcA = gAp + (size_t)ra * KX2 + k0 + g * 8;
    asm volatile("cp.async.cg.shared.global [%0], [%1], 16, %2;"
                 :: "r"(sA + soff), "l"(srcA), "r"(sza));
    int rb = min(j0 + row, NR - 1);
    int szb = (j0 + row < NR) ? 16 : 0;
    const void* srcB = gBp + (size_t)rb * KX2 + k0 + g * 8;
    asm volatile("cp.async.cg.shared.global [%0], [%1], 16, %2;"
                 :: "r"(sB + soff), "l"(srcB), "r"(szb));
  }
  asm volatile("cp.async.commit_group;" ::: "memory");
}

__global__ __launch_bounds__(256, 2) void k_gemm() {
  extern __shared__ __align__(128) char sm[];
  uint32_t sb = smem_u32(sm);
  int tid = threadIdx.x, lane = tid & 31, wid = tid >> 5;
  int wr = wid >> 2, wc = wid & 3;         // 2 x 4 warp grid; warp tile 64 x 32

  // ---- tile decode ----
  int t = blockIdx.x, z, by, bx;
  if (t < 225) { z = 0; by = t / 15; bx = t % 15; }
  else {
    int u = t - 225;
    z = 1 + u / 120;
    int v = u % 120;
    by = 0;
    while (v >= 15 - by) { v -= 15 - by; by++; }
    bx = by + v;
  }
  bool offdiag = (z != 0) && (bx != by);
  int i0 = by * 128, j0 = bx * 128;
  const __half* __restrict__ Ag = g_g[c_AS[z]];
  const __half* __restrict__ Bg = g_g[c_BS[z]];

  if (tid < 128) {
    int gi = i0 + tid, gj = j0 + tid;
    ((int*)(sm + SM_CLSR))[tid] = (gi < NR) ? (gi / NVIEW) % NCLS_ : -2;
    ((int*)(sm + SM_CLSC))[tid] = (gj < NR) ? (gj / NVIEW) % NCLS_ : -1;
  }

  float acc[4][4][4];
  #pragma unroll
  for (int a = 0; a < 4; a++)
    #pragma unroll
    for (int b = 0; b < 4; b++)
      #pragma unroll
      for (int c = 0; c < 4; c++) acc[a][b][c] = 0.f;

  ld_stage(sb + SM_AS(0), sb + SM_BS(0), Ag, Bg, i0, j0, 0);

  #pragma unroll 1
  for (int ch = 0; ch < NCHUNK; ch++) {
    __syncthreads();
    if (ch + 1 < NCHUNK) {
      ld_stage(sb + SM_AS((ch + 1) & 1), sb + SM_BS((ch + 1) & 1), Ag, Bg, i0, j0, ch + 1);
      asm volatile("cp.async.wait_group 1;" ::: "memory");
    } else {
      asm volatile("cp.async.wait_group 0;" ::: "memory");
    }
    __syncthreads();
    uint32_t sA = sb + SM_AS(ch & 1), sB = sb + SM_BS(ch & 1);

    #pragma unroll
    for (int ks = 0; ks < 4; ks++) {
      uint32_t af[4][4], bf[2][4];
      #pragma unroll
      for (int mt = 0; mt < 4; mt++) {
        int r = wr * 64 + mt * 16 + (lane & 15);
        uint32_t addr = sA + r * 128 + ((ks * 32 + (lane >> 4) * 16) ^ ((r & 7) << 4));
        asm volatile("ldmatrix.sync.aligned.m8n8.x4.shared.b16 {%0,%1,%2,%3}, [%4];"
                     : "=r"(af[mt][0]), "=r"(af[mt][1]), "=r"(af[mt][2]), "=r"(af[mt][3])
                     : "r"(addr));
      }
      #pragma unroll
      for (int np = 0; np < 2; np++) {
        int n = wc * 32 + np * 16 + (lane & 15);
        uint32_t addr = sB + n * 128 + ((ks * 32 + (lane >> 4) * 16) ^ ((n & 7) << 4));
        asm volatile("ldmatrix.sync.aligned.m8n8.x4.shared.b16 {%0,%1,%2,%3}, [%4];"
                     : "=r"(bf[np][0]), "=r"(bf[np][1]), "=r"(bf[np][2]), "=r"(bf[np][3])
                     : "r"(addr));
      }
      #pragma unroll
      for (int mt = 0; mt < 4; mt++)
        #pragma unroll
        for (int nt = 0; nt < 4; nt++) {
          uint32_t b0 = bf[nt >> 1][nt & 1], b1 = bf[nt >> 1][(nt & 1) + 2];
          asm volatile("mma.sync.aligned.m16n8k16.row.col.f32.f16.f16.f32 "
                       "{%0,%1,%2,%3}, {%4,%5,%6,%7}, {%8,%9}, {%0,%1,%2,%3};"
                       : "+f"(acc[mt][nt][0]), "+f"(acc[mt][nt][1]),
                         "+f"(acc[mt][nt][2]), "+f"(acc[mt][nt][3])
                       : "r"(af[mt][0]), "r"(af[mt][1]), "r"(af[mt][2]), "r"(af[mt][3]),
                         "r"(b0), "r"(b1));
        }
    }
  }

  // ---- epilogue: masked exp; row sums always, col sums for symmetric off-diagonal ----
  __syncthreads();
  const int* clsR = (const int*)(sm + SM_CLSR);
  const int* clsC = (const int*)(sm + SM_CLSC);
  float* spart = (float*)(sm + SM_SPART);
  float* cpart = (float*)(sm + SM_CPART);

  float ec[4][2];
  #pragma unroll
  for (int nt = 0; nt < 4; nt++) { ec[nt][0] = 0.f; ec[nt][1] = 0.f; }

  #pragma unroll
  for (int mt = 0; mt < 4; mt++) {
    int rl = wr * 64 + mt * 16 + (lane >> 2);
    int cr0 = clsR[rl], cr1 = clsR[rl + 8];
    float es0 = 0.f, es1 = 0.f;
    #pragma unroll
    for (int nt = 0; nt < 4; nt++) {
      int cl = wc * 32 + nt * 8 + (lane & 3) * 2;
      int cc0 = clsC[cl], cc1 = clsC[cl + 1];
      float e00 = (cc0 >= 0 && cr0 >= 0 && cc0 != cr0) ? __expf(acc[mt][nt][0] * 10.0f) : 0.f;
      float e01 = (cc1 >= 0 && cr0 >= 0 && cc1 != cr0) ? __expf(acc[mt][nt][1] * 10.0f) : 0.f;
      float e10 = (cc0 >= 0 && cr1 >= 0 && cc0 != cr1) ? __expf(acc[mt][nt][2] * 10.0f) : 0.f;
      float e11 = (cc1 >= 0 && cr1 >= 0 && cc1 != cr1) ? __expf(acc[mt][nt][3] * 10.0f) : 0.f;
      es0 += e00 + e01;
      es1 += e10 + e11;
      ec[nt][0] += e00 + e10;
      ec[nt][1] += e01 + e11;
    }
    es0 += __shfl_xor_sync(0xffffffffu, es0, 1);
    es0 += __shfl_xor_sync(0xffffffffu, es0, 2);
    es1 += __shfl_xor_sync(0xffffffffu, es1, 1);
    es1 += __shfl_xor_sync(0xffffffffu, es1, 2);
    if ((lane & 3) == 0) {
      spart[wc * 128 + rl] = es0;
      spart[wc * 128 + rl + 8] = es1;
    }
  }
  if (offdiag) {
    #pragma unroll
    for (int nt = 0; nt < 4; nt++) {
      #pragma unroll
      for (int h = 0; h < 2; h++) {
        float v = ec[nt][h];
        v += __shfl_xor_sync(0xffffffffu, v, 4);
        v += __shfl_xor_sync(0xffffffffu, v, 8);
        v += __shfl_xor_sync(0xffffffffu, v, 16);
        if ((lane >> 2) == 0) {
          int cl = wc * 32 + nt * 8 + (lane & 3) * 2 + h;
          cpart[wr * 128 + cl] = v;
        }
      }
    }
  }
  __syncthreads();
  if (tid < 128) {
    int gi = i0 + tid;
    if (gi < NR) {
      float s = spart[tid] + spart[128 + tid] + spart[256 + tid] + spart[384 + tid];
      g_Spart[z][gi * 16 + bx] = s;
    }
    if (offdiag) {
      int gj = j0 + tid;
      if (gj < NR) g_Spart[z][gj * 16 + by] = cpart[tid] + cpart[128 + tid];
    }
  }
}

// ---------------- K5: per-class positive block + InfoNCE (hi+lo reconstructed) ----------------
__device__ __forceinline__ int gRow(int ci, int r) {
  return (r < NVIEW) ? ci * NVIEW + r : (NR / 2) + ci * NVIEW + (r - NVIEW);
}

__global__ __launch_bounds__(256) void k_loss() {
  int ci = blockIdx.x, z = blockIdx.y;
  const __half* __restrict__ A = g_g[c_AS[z]];
  const __half* __restrict__ B = g_g[c_BS[z]];
  __shared__ float As[112][33], Bs[112][33];
  __shared__ float Sneg[112], part[100][16], rl[100];
  int tid = threadIdx.x, tx = tid & 15, ty = tid >> 4;

  if (tid < 100) {
    int gi = gRow(ci, tid);
    float s = 0.f;
    #pragma unroll
    for (int c = 0; c < 15; c++) s += g_Spart[z][gi * 16 + c];
    Sneg[tid] = s;
  }

  float acc[7][7];
  #pragma unroll
  for (int u = 0; u < 7; u++)
    #pragma unroll
    for (int v = 0; v < 7; v++) acc[u][v] = 0.f;

  #pragma unroll 1
  for (int k0 = 0; k0 < NCH; k0 += 32) {
    __syncthreads();
    for (int idx = tid; idx < 112 * 32; idx += 256) {
      int r = idx >> 5, c = idx & 31;
      float av = 0.f, bv = 0.f;
      if (r < 100) {
        int g = gRow(ci, r);
        const __half* ap = &A[(size_t)g * KX2 + k0 + c];
        const __half* bp = &B[(size_t)g * KX2 + k0 + c];
        av = __half2float(ap[0]) + __half2float(ap[256]);
        bv = __half2float(bp[0]) + __half2float(bp[256]);
      }
      As[r][c] = av;
      Bs[r][c] = bv;
    }
    __syncthreads();
    #pragma unroll
    for (int kk = 0; kk < 32; kk++) {
      float av[7], bv[7];
      #pragma unroll
      for (int u = 0; u < 7; u++) av[u] = As[ty * 7 + u][kk];
      #pragma unroll
      for (int v = 0; v < 7; v++) bv[v] = Bs[tx * 7 + v][kk];
      #pragma unroll
      for (int u = 0; u < 7; u++)
        #pragma unroll
        for (int v = 0; v < 7; v++) acc[u][v] = fmaf(av[u], bv[v], acc[u][v]);
    }
  }
  __syncthreads();
  #pragma unroll
  for (int u = 0; u < 7; u++) {
    int i = ty * 7 + u;
    if (i < 100) {
      float sn = Sneg[i];
      float ps = 0.f;
      #pragma unroll
      for (int v = 0; v < 7; v++) {
        int j = tx * 7 + v;
        if (j < 100 && j != i) {
          float d10 = acc[u][v] * 10.0f;
          ps += d10 - logf(expf(d10) + sn);
        }
      }
      part[i][tx] = ps;
    }
  }
  __syncthreads();
  if (tid < 100) {
    float s = 0.f;
    #pragma unroll
    for (int c = 0; c < 16; c++) s += part[tid][c];
    rl[tid] = s;
  }
  __syncthreads();
  if (tid == 0) {
    float tot = 0.f;
    for (int i = 0; i < 100; i++) tot += rl[i];
    g_classloss[z * NCLS_ + ci] = -tot / 99.0f;
  }
}

// ---------------- K6: final ----------------
__global__ void k_final(float* __restrict__ out) {
  int tid = threadIdx.x;
  if (tid < 3) {
    float s = 0.f;
    for (int c = 0; c < NCLS_; c++) s += g_classloss[tid * NCLS_ + c];
    out[tid] = s / (float)NR;
  }
}

// ---------------- launch ----------------
extern "C" void kernel_launch(void* const* d_in, const int* in_sizes, int n_in,
                              void* d_out, int out_size) {
  const int*   label  = (const int*)d_in[0];
  const float* colorf = (const float*)d_in[1];
  const float* otherf = (const float*)d_in[2];
  float* out = (float*)d_out;

  cudaFuncSetAttribute(k_gemm, cudaFuncAttributeMaxDynamicSharedMemorySize, GEMM_SMEM);

  k_zero<<<1, 64>>>();
  k_keys<<<HW_ / 256, 256>>>(label);
  k_select<<<NT, 256>>>(label);
  k_gather<<<dim3(NR, 2), 256>>>(colorf, otherf);
  k_gemm<<<NTILES, 256, GEMM_SMEM>>>();
  k_loss<<<dim3(NCLS_, 3), 256>>>();
  k_final<<<1, 32>>>(out);
}

// round 15
// speedup vs baseline: 2.5505x; 1.0440x over previous
#include <cuda_runtime.h>
#include <cuda_fp16.h>
#include <stdint.h>
#include <math.h>

// ---------------- problem constants ----------------
#define HW_    32768
#define NCLS_  19
#define NVIEW  50
#define NT     38
#define NR     1900
#define NCH    256
#define KX2    512          // [hi | lo] fp16 per row

// ---------------- scratch ----------------
__device__ unsigned long long g_list[(size_t)NT * HW_];
__device__ int   g_cnt[NT];                          // reset by k_select each run
__device__ int   g_sel[NT * NVIEW];
__device__ __half g_g[2][(size_t)NR * KX2];          // [hi(256) | lo(256)] per row per modality
__device__ float g_Spart[3][NR * 16];                // 15 slots of 128-col tiles

__device__ __constant__ int c_AS[3] = {0, 0, 1};
__device__ __constant__ int c_BS[3] = {1, 0, 1};

// ---------------- threefry2x32, key (0, 42) ----------------
__device__ __forceinline__ void threefry2x32(uint32_t c0, uint32_t c1,
                                             uint32_t &o0, uint32_t &o1) {
  const uint32_t ks0 = 0u, ks1 = 42u;
  const uint32_t ks2 = 0u ^ 42u ^ 0x1BD11BDAu;
  uint32_t x0 = c0 + ks0, x1 = c1 + ks1;
#define TFR(r) { x0 += x1; x1 = (x1 << (r)) | (x1 >> (32 - (r))); x1 ^= x0; }
  TFR(13) TFR(15) TFR(26) TFR(6)
  x0 += ks1; x1 += ks2 + 1u;
  TFR(17) TFR(29) TFR(16) TFR(24)
  x0 += ks2; x1 += ks0 + 2u;
  TFR(13) TFR(15) TFR(26) TFR(6)
  x0 += ks0; x1 += ks1 + 3u;
  TFR(17) TFR(29) TFR(16) TFR(24)
  x0 += ks1; x1 += ks2 + 4u;
  TFR(13) TFR(15) TFR(26) TFR(6)
  x0 += ks2; x1 += ks0 + 5u;
#undef TFR
  o0 = x0; o1 = x1;
}

__device__ __forceinline__ uint32_t smem_u32(const void* p) {
  uint32_t a;
  asm("{ .reg .u64 t; cvta.to.shared.u64 t, %1; cvt.u32.u64 %0, t; }" : "=r"(a) : "l"(p));
  return a;
}

// ---------------- K1: keys + hierarchical per-class compaction (+ zero out) ----------------
__global__ __launch_bounds__(256) void k_keys(const int* __restrict__ label,
                                              float* __restrict__ out) {
  __shared__ int scnt[NT], sbase[NT];
  int tid = threadIdx.x;
  if (blockIdx.x == 0 && tid < 3) out[tid] = 0.f;    // k_loss accumulates into out
  if (tid < NT) scnt[tid] = 0;
  __syncthreads();
  int hw = blockIdx.x * 256 + tid;
  uint32_t o0, o1;
  threefry2x32((uint32_t)hw, (uint32_t)(hw + HW_), o0, o1);
  int l0 = label[(hw >> 8) * 4096 + (hw & 255) * 4];
  int l1 = label[524288 + (hw >> 8) * 4096 + (hw & 255) * 4];
  int t0 = l0, t1 = NCLS_ + l1;
  unsigned long long k0 = ((unsigned long long)(o0 >> 9) << 32) | (unsigned)hw;
  unsigned long long k1 = ((unsigned long long)(o1 >> 9) << 32) | (unsigned)hw;
  int r0 = atomicAdd(&scnt[t0], 1);
  int r1 = atomicAdd(&scnt[t1], 1);
  __syncthreads();
  if (tid < NT && scnt[tid] > 0) sbase[tid] = atomicAdd(&g_cnt[tid], scnt[tid]);
  __syncthreads();
  g_list[(size_t)t0 * HW_ + sbase[t0] + r0] = k0;
  g_list[(size_t)t1 * HW_ + sbase[t1] + r1] = k1;
}

// ---------------- K2: histogram top-50 select (warp-parallel tail) ----------------
__global__ __launch_bounds__(256) void k_select(const int* __restrict__ label) {
  int t = blockIdx.x, tid = threadIdx.x;
  int cnt = g_cnt[t];
  int lim = min(cnt, NVIEW);
  const unsigned long long* lst = &g_list[(size_t)t * HW_];
  __shared__ int hist[256];
  __shared__ unsigned long long cand[256];
  __shared__ int ncand, nsel, sbin, sneed;
  hist[tid] = 0;
  if (tid == 0) { ncand = 0; nsel = 0; }
  __syncthreads();
  for (int i = tid; i < cnt; i += 256) atomicAdd(&hist[(int)(lst[i] >> 47)], 1);
  __syncthreads();
  if (tid == 0) {
    int cum = 0, b = 0;
    for (; b < 256; b++) { if (cum + hist[b] >= lim) break; cum += hist[b]; }
    sbin = b; sneed = lim - cum;
  }
  __syncthreads();
  int B = sbin;
  for (int i = tid; i < cnt; i += 256) {
    unsigned long long k = lst[i];
    int b = (int)(k >> 47);
    if (b < B) { int p = atomicAdd(&nsel, 1); g_sel[t * NVIEW + p] = (int)(k & 0xffffffffu); }
    else if (b == B) { int p = atomicAdd(&ncand, 1); if (p < 256) cand[p] = k; }
  }
  __syncthreads();
  // warp 0: parallel repeated-min over boundary-bin candidates
  if (tid < 32) {
    int base = nsel, nc = min(ncand, 256), need = sneed;
    for (int r = 0; r < need; r++) {
      unsigned long long best = ~0ull;
      int bi = -1;
      for (int q = tid; q < nc; q += 32) {
        unsigned long long k = cand[q];
        if (k < best) { best = k; bi = q; }
      }
      #pragma unroll
      for (int o = 16; o; o >>= 1) {
        unsigned long long ob = __shfl_xor_sync(0xffffffffu, best, o);
        int obi = __shfl_xor_sync(0xffffffffu, bi, o);
        if (ob < best) { best = ob; bi = obi; }
      }
      if (tid == 0) {
        cand[bi] = ~0ull;
        g_sel[t * NVIEW + base + r] = (int)(best & 0xffffffffu);
      }
      __syncwarp();
    }
  }
  // pad (never triggers for this input) + reset counter for next graph replay
  if (tid == 0) {
    if (cnt < NVIEW) {
      int n = t / NCLS_, cls = t % NCLS_, fill = cnt;
      for (int hw = 0; hw < HW_ && fill < NVIEW; hw++) {
        int lbl = label[n * 524288 + (hw >> 8) * 4096 + (hw & 255) * 4];
        if (lbl != cls) g_sel[t * NVIEW + fill++] = hw;
      }
    }
    g_cnt[t] = 0;
  }
}

// ---------------- K3: gather + normalize + hi/lo fp16 (both modalities per block) ----------------
__global__ __launch_bounds__(256) void k_gather(const float* __restrict__ colorf,
                                                const float* __restrict__ otherf) {
  int row = blockIdx.x;
  int t = row / NVIEW, v = row % NVIEW, n = t / NCLS_;
  int p = g_sel[t * NVIEW + v];
  int ch = threadIdx.x;
  size_t off = ((size_t)n * NCH + ch) * HW_ + p;
  float vc = colorf[off];
  float vo = otherf[off];
  float sc = vc * vc, so = vo * vo;
  #pragma unroll
  for (int o = 16; o; o >>= 1) {
    sc += __shfl_xor_sync(0xffffffffu, sc, o);
    so += __shfl_xor_sync(0xffffffffu, so, o);
  }
  __shared__ float ws[16];
  if ((ch & 31) == 0) { ws[ch >> 5] = sc; ws[8 + (ch >> 5)] = so; }
  __syncthreads();
  __shared__ float s_invc, s_invo;
  if (ch == 0) {
    float a = 0.f, b = 0.f;
    #pragma unroll
    for (int i = 0; i < 8; i++) { a += ws[i]; b += ws[8 + i]; }
    s_invc = 1.0f / fmaxf(sqrtf(a), 1e-12f);
    s_invo = 1.0f / fmaxf(sqrtf(b), 1e-12f);
  }
  __syncthreads();
  float nc = vc * s_invc, no = vo * s_invo;
  __half hic = __float2half(nc);
  __half loc_ = __float2half(nc - __half2float(hic));
  __half hio = __float2half(no);
  __half loo = __float2half(no - __half2float(hio));
  __half* gc = &g_g[0][(size_t)row * KX2];
  __half* go = &g_g[1][(size_t)row * KX2];
  gc[ch] = hic;  gc[256 + ch] = loc_;
  go[ch] = hio;  go[256 + ch] = loo;
}

// ---------------- K4: mma.sync fp16 GEMM (single hi pass, K=256) + fused S_neg epilogue ----------------
#define SM_AS(st)  ((st) * 16384)
#define SM_BS(st)  (32768 + (st) * 16384)
#define SM_SPART   65536             // 512 f32 row partials
#define SM_CPART   67584             // 256 f32 col partials
#define SM_CLSR    68608             // 128 i32
#define SM_CLSC    69120             // 128 i32
#define GEMM_SMEM  69632
#define NCHUNK     4
#define NTILES     465

__device__ __forceinline__ void ld_stage(uint32_t sA, uint32_t sB,
                                         const __half* __restrict__ gAp,
                                         const __half* __restrict__ gBp,
                                         int i0, int j0, int ch) {
  int tid = threadIdx.x;
  int k0 = ch * 64;                        // hi block only (first 256 halves)
  #pragma unroll
  for (int e = 0; e < 4; e++) {
    int idx = tid + e * 256;               // 128 rows x 8 groups of 16B
    int row = idx >> 3, g = idx & 7;
    uint32_t soff = row * 128 + ((g * 16) ^ ((row & 7) << 4));
    int ra = min(i0 + row, NR - 1);
    int sza = (i0 + row < NR) ? 16 : 0;
    const void* srcA = gAp + (size_t)ra * KX2 + k0 + g * 8;
    asm volatile("cp.async.cg.shared.global [%0], [%1], 16, %2;"
                 :: "r"(sA + soff), "l"(srcA), "r"(sza));
    int rb = min(j0 + row, NR - 1);
    int szb = (j0 + row < NR) ? 16 : 0;
    const void* srcB = gBp + (size_t)rb * KX2 + k0 + g * 8;
    asm volatile("cp.async.cg.shared.global [%0], [%1], 16, %2;"
                 :: "r"(sB + soff), "l"(srcB), "r"(szb));
  }
  asm volatile("cp.async.commit_group;" ::: "memory");
}

__global__ __launch_bounds__(256, 2) void k_gemm() {
  extern __shared__ __align__(128) char sm[];
  uint32_t sb = smem_u32(sm);
  int tid = threadIdx.x, lane = tid & 31, wid = tid >> 5;
  int wr = wid >> 2, wc = wid & 3;         // 2 x 4 warp grid; warp tile 64 x 32

  // ---- tile decode ----
  int t = blockIdx.x, z, by, bx;
  if (t < 225) { z = 0; by = t / 15; bx = t % 15; }
  else {
    int u = t - 225;
    z = 1 + u / 120;
    int v = u % 120;
    by = 0;
    while (v >= 15 - by) { v -= 15 - by; by++; }
    bx = by + v;
  }
  bool offdiag = (z != 0) && (bx != by);
  int i0 = by * 128, j0 = bx * 128;
  const __half* __restrict__ Ag = g_g[c_AS[z]];
  const __half* __restrict__ Bg = g_g[c_BS[z]];

  if (tid < 128) {
    int gi = i0 + tid, gj = j0 + tid;
    ((int*)(sm + SM_CLSR))[tid] = (gi < NR) ? (gi / NVIEW) % NCLS_ : -2;
    ((int*)(sm + SM_CLSC))[tid] = (gj < NR) ? (gj / NVIEW) % NCLS_ : -1;
  }

  float acc[4][4][4];
  #pragma unroll
  for (int a = 0; a < 4; a++)
    #pragma unroll
    for (int b = 0; b < 4; b++)
      #pragma unroll
      for (int c = 0; c < 4; c++) acc[a][b][c] = 0.f;

  ld_stage(sb + SM_AS(0), sb + SM_BS(0), Ag, Bg, i0, j0, 0);

  #pragma unroll 1
  for (int ch = 0; ch < NCHUNK; ch++) {
    __syncthreads();
    if (ch + 1 < NCHUNK) {
      ld_stage(sb + SM_AS((ch + 1) & 1), sb + SM_BS((ch + 1) & 1), Ag, Bg, i0, j0, ch + 1);
      asm volatile("cp.async.wait_group 1;" ::: "memory");
    } else {
      asm volatile("cp.async.wait_group 0;" ::: "memory");
    }
    __syncthreads();
    uint32_t sA = sb + SM_AS(ch & 1), sB = sb + SM_BS(ch & 1);

    #pragma unroll
    for (int ks = 0; ks < 4; ks++) {
      uint32_t af[4][4], bf[2][4];
      #pragma unroll
      for (int mt = 0; mt < 4; mt++) {
        int r = wr * 64 + mt * 16 + (lane & 15);
        uint32_t addr = sA + r * 128 + ((ks * 32 + (lane >> 4) * 16) ^ ((r & 7) << 4));
        asm volatile("ldmatrix.sync.aligned.m8n8.x4.shared.b16 {%0,%1,%2,%3}, [%4];"
                     : "=r"(af[mt][0]), "=r"(af[mt][1]), "=r"(af[mt][2]), "=r"(af[mt][3])
                     : "r"(addr));
      }
      #pragma unroll
      for (int np = 0; np < 2; np++) {
        int n = wc * 32 + np * 16 + (lane & 15);
        uint32_t addr = sB + n * 128 + ((ks * 32 + (lane >> 4) * 16) ^ ((n & 7) << 4));
        asm volatile("ldmatrix.sync.aligned.m8n8.x4.shared.b16 {%0,%1,%2,%3}, [%4];"
                     : "=r"(bf[np][0]), "=r"(bf[np][1]), "=r"(bf[np][2]), "=r"(bf[np][3])
                     : "r"(addr));
      }
      #pragma unroll
      for (int mt = 0; mt < 4; mt++)
        #pragma unroll
        for (int nt = 0; nt < 4; nt++) {
          uint32_t b0 = bf[nt >> 1][nt & 1], b1 = bf[nt >> 1][(nt & 1) + 2];
          asm volatile("mma.sync.aligned.m16n8k16.row.col.f32.f16.f16.f32 "
                       "{%0,%1,%2,%3}, {%4,%5,%6,%7}, {%8,%9}, {%0,%1,%2,%3};"
                       : "+f"(acc[mt][nt][0]), "+f"(acc[mt][nt][1]),
                         "+f"(acc[mt][nt][2]), "+f"(acc[mt][nt][3])
                       : "r"(af[mt][0]), "r"(af[mt][1]), "r"(af[mt][2]), "r"(af[mt][3]),
                         "r"(b0), "r"(b1));
        }
    }
  }

  // ---- epilogue: masked exp; row sums always, col sums for symmetric off-diagonal ----
  __syncthreads();
  const int* clsR = (const int*)(sm + SM_CLSR);
  const int* clsC = (const int*)(sm + SM_CLSC);
  float* spart = (float*)(sm + SM_SPART);
  float* cpart = (float*)(sm + SM_CPART);

  float ec[4][2];
  #pragma unroll
  for (int nt = 0; nt < 4; nt++) { ec[nt][0] = 0.f; ec[nt][1] = 0.f; }

  #pragma unroll
  for (int mt = 0; mt < 4; mt++) {
    int rl = wr * 64 + mt * 16 + (lane >> 2);
    int cr0 = clsR[rl], cr1 = clsR[rl + 8];
    float es0 = 0.f, es1 = 0.f;
    #pragma unroll
    for (int nt = 0; nt < 4; nt++) {
      int cl = wc * 32 + nt * 8 + (lane & 3) * 2;
      int cc0 = clsC[cl], cc1 = clsC[cl + 1];
      float e00 = (cc0 >= 0 && cr0 >= 0 && cc0 != cr0) ? __expf(acc[mt][nt][0] * 10.0f) : 0.f;
      float e01 = (cc1 >= 0 && cr0 >= 0 && cc1 != cr0) ? __expf(acc[mt][nt][1] * 10.0f) : 0.f;
      float e10 = (cc0 >= 0 && cr1 >= 0 && cc0 != cr1) ? __expf(acc[mt][nt][2] * 10.0f) : 0.f;
      float e11 = (cc1 >= 0 && cr1 >= 0 && cc1 != cr1) ? __expf(acc[mt][nt][3] * 10.0f) : 0.f;
      es0 += e00 + e01;
      es1 += e10 + e11;
      ec[nt][0] += e00 + e10;
      ec[nt][1] += e01 + e11;
    }
    es0 += __shfl_xor_sync(0xffffffffu, es0, 1);
    es0 += __shfl_xor_sync(0xffffffffu, es0, 2);
    es1 += __shfl_xor_sync(0xffffffffu, es1, 1);
    es1 += __shfl_xor_sync(0xffffffffu, es1, 2);
    if ((lane & 3) == 0) {
      spart[wc * 128 + rl] = es0;
      spart[wc * 128 + rl + 8] = es1;
    }
  }
  if (offdiag) {
    #pragma unroll
    for (int nt = 0; nt < 4; nt++) {
      #pragma unroll
      for (int h = 0; h < 2; h++) {
        float v = ec[nt][h];
        v += __shfl_xor_sync(0xffffffffu, v, 4);
        v += __shfl_xor_sync(0xffffffffu, v, 8);
        v += __shfl_xor_sync(0xffffffffu, v, 16);
        if ((lane >> 2) == 0) {
          int cl = wc * 32 + nt * 8 + (lane & 3) * 2 + h;
          cpart[wr * 128 + cl] = v;
        }
      }
    }
  }
  __syncthreads();
  if (tid < 128) {
    int gi = i0 + tid;
    if (gi < NR) {
      float s = spart[tid] + spart[128 + tid] + spart[256 + tid] + spart[384 + tid];
      g_Spart[z][gi * 16 + bx] = s;
    }
    if (offdiag) {
      int gj = j0 + tid;
      if (gj < NR) g_Spart[z][gj * 16 + by] = cpart[tid] + cpart[128 + tid];
    }
  }
}

// ---------------- K5: per-class positive block + InfoNCE -> atomic into out ----------------
__device__ __forceinline__ int gRow(int ci, int r) {
  return (r < NVIEW) ? ci * NVIEW + r : (NR / 2) + ci * NVIEW + (r - NVIEW);
}

__global__ __launch_bounds__(256) void k_loss(float* __restrict__ out) {
  int ci = blockIdx.x, z = blockIdx.y;
  const __half* __restrict__ A = g_g[c_AS[z]];
  const __half* __restrict__ B = g_g[c_BS[z]];
  __shared__ float As[112][33], Bs[112][33];
  __shared__ float Sneg[112], part[100][16], rl[100];
  int tid = threadIdx.x, tx = tid & 15, ty = tid >> 4;

  if (tid < 100) {
    int gi = gRow(ci, tid);
    float s = 0.f;
    #pragma unroll
    for (int c = 0; c < 15; c++) s += g_Spart[z][gi * 16 + c];
    Sneg[tid] = s;
  }

  float acc[7][7];
  #pragma unroll
  for (int u = 0; u < 7; u++)
    #pragma unroll
    for (int v = 0; v < 7; v++) acc[u][v] = 0.f;

  #pragma unroll 1
  for (int k0 = 0; k0 < NCH; k0 += 32) {
    __syncthreads();
    for (int idx = tid; idx < 112 * 32; idx += 256) {
      int r = idx >> 5, c = idx & 31;
      float av = 0.f, bv = 0.f;
      if (r < 100) {
        int g = gRow(ci, r);
        const __half* ap = &A[(size_t)g * KX2 + k0 + c];
        const __half* bp = &B[(size_t)g * KX2 + k0 + c];
        av = __half2float(ap[0]) + __half2float(ap[256]);
        bv = __half2float(bp[0]) + __half2float(bp[256]);
      }
      As[r][c] = av;
      Bs[r][c] = bv;
    }
    __syncthreads();
    #pragma unroll
    for (int kk = 0; kk < 32; kk++) {
      float av[7], bv[7];
      #pragma unroll
      for (int u = 0; u < 7; u++) av[u] = As[ty * 7 + u][kk];
      #pragma unroll
      for (int v = 0; v < 7; v++) bv[v] = Bs[tx * 7 + v][kk];
      #pragma unroll
      for (int u = 0; u < 7; u++)
        #pragma unroll
        for (int v = 0; v < 7; v++) acc[u][v] = fmaf(av[u], bv[v], acc[u][v]);
    }
  }
  __syncthreads();
  #pragma unroll
  for (int u = 0; u < 7; u++) {
    int i = ty * 7 + u;
    if (i < 100) {
      float sn = Sneg[i];
      float ps = 0.f;
      #pragma unroll
      for (int v = 0; v < 7; v++) {
        int j = tx * 7 + v;
        if (j < 100 && j != i) {
          float d10 = acc[u][v] * 10.0f;
          ps += d10 - logf(expf(d10) + sn);
        }
      }
      part[i][tx] = ps;
    }
  }
  __syncthreads();
  if (tid < 100) {
    float s = 0.f;
    #pragma unroll
    for (int c = 0; c < 16; c++) s += part[tid][c];
    rl[tid] = s;
  }
  __syncthreads();
  if (tid == 0) {
    float tot = 0.f;
    for (int i = 0; i < 100; i++) tot += rl[i];
    atomicAdd(&out[z], -tot / (99.0f * (float)NR));
  }
}

// ---------------- launch ----------------
extern "C" void kernel_launch(void* const* d_in, const int* in_sizes, int n_in,
                              void* d_out, int out_size) {
  const int*   label  = (const int*)d_in[0];
  const float* colorf = (const float*)d_in[1];
  const float* otherf = (const float*)d_in[2];
  float* out = (float*)d_out;

  cudaFuncSetAttribute(k_gemm, cudaFuncAttributeMaxDynamicSharedMemorySize, GEMM_SMEM);

  k_keys<<<HW_ / 256, 256>>>(label, out);
  k_select<<<NT, 256>>>(label);
  k_gather<<<NR, 256>>>(colorf, otherf);
  k_gemm<<<NTILES, 256, GEMM_SMEM>>>();
  k_loss<<<dim3(NCLS_, 3), 256>>>(out);
}